// round 6
// baseline (speedup 1.0000x reference)
#include <cuda_runtime.h>
#include <cstdint>

#define IN_FEATURES  4096
#define OUT_FEATURES 11008
#define WORDS        (IN_FEATURES / 8)        // 512 packed int32 rows
#define BLOCK_THREADS 256
#define OUTS_PER_BLOCK 32
#define KSLICES 8                             // warps per block
#define KSPLIT  4                             // K-quarters across blockIdx.y
#define WORDS_PER_BLOCK (WORDS / KSPLIT)      // 128
#define WORDS_PER_WARP  (WORDS_PER_BLOCK / KSLICES)  // 16
#define XS_FLOATS (WORDS_PER_BLOCK * 8)       // 1024 floats staged per block

// Deterministic cross-block scratch (device globals are the allowed scratch).
__device__ float g_part[KSPLIT][OUT_FEATURES];
__device__ float g_xsum[KSPLIT];

// Packed constants: two fp32 lanes of -8388608.0f (0xCB000000)
#define NEG_MAGIC2 0xCB000000CB000000ull

// One packed pair of nibble-MACs:
//   lo = float(8388608 + nib_even)  from byte SEL of e
//   hi = float(8388608 + nib_odd)   from byte SEL of h
//   f2 = (lo,hi) - (2^23,2^23)      exact (Sterbenz)
//   acc2 += xpair * f2
template <unsigned SEL>
__device__ __forceinline__ void qfma2(unsigned long long& acc,
                                      unsigned e, unsigned h,
                                      unsigned long long xpair) {
    asm("{\n\t"
        ".reg .b32 lo, hi;\n\t"
        ".reg .b64 f2;\n\t"
        "prmt.b32 lo, %1, 0x4B000000, %3;\n\t"
        "prmt.b32 hi, %2, 0x4B000000, %3;\n\t"
        "mov.b64 f2, {lo, hi};\n\t"
        "add.rn.f32x2 f2, f2, %4;\n\t"
        "fma.rn.f32x2 %0, f2, %5, %0;\n\t"
        "}"
        : "+l"(acc)
        : "r"(e), "r"(h), "n"(SEL), "l"(NEG_MAGIC2), "l"(xpair));
}

__device__ __forceinline__ float2 ull_as_f2(unsigned long long a) {
    float2 r;
    r.x = __uint_as_float((unsigned)(a & 0xFFFFFFFFull));
    r.y = __uint_as_float((unsigned)(a >> 32));
    return r;
}

__global__ __launch_bounds__(BLOCK_THREADS, 4)
void quant4linear_main(const float* __restrict__ x,
                       const int*   __restrict__ qweight) {
    __shared__ __align__(16) float xs[XS_FLOATS];
    __shared__ float wxsum[KSLICES];
    __shared__ float part[KSLICES][OUTS_PER_BLOCK];

    const int tid     = threadIdx.x;
    const int o_local = tid & 31;
    const int ksl     = tid >> 5;
    const int kbase   = blockIdx.y * WORDS_PER_BLOCK;   // word row of this block

    // ---- Stage this block's x slice (1024 floats) + partial x-sum ----
    float s = 0.0f;
    #pragma unroll
    for (int i = tid; i < XS_FLOATS; i += BLOCK_THREADS) {
        float v = x[kbase * 8 + i];
        xs[i] = v;
        s += v;
    }
    #pragma unroll
    for (int off = 16; off; off >>= 1)
        s += __shfl_down_sync(0xFFFFFFFFu, s, off);
    if (o_local == 0) wxsum[ksl] = s;
    __syncthreads();  // xs + wxsum visible

    // ---- Main loop: lane = output channel, warp = K-sub-slice ----
    const int o = blockIdx.x * OUTS_PER_BLOCK + o_local;

    const int* wp = qweight + (kbase + ksl * WORDS_PER_WARP) * OUT_FEATURES + o;
    // x pairs for local word k live at ulonglong2 indices [2k, 2k+1]
    const ulonglong2* xp =
        reinterpret_cast<const ulonglong2*>(xs) + (ksl * WORDS_PER_WARP) * 2;

    unsigned long long acc0 = 0, acc1 = 0, acc2 = 0, acc3 = 0;

    #pragma unroll 8
    for (int i = 0; i < WORDS_PER_WARP; i++) {
        unsigned w = (unsigned)__ldg(wp);
        wp += OUT_FEATURES;
        unsigned e = w & 0x0F0F0F0Fu;          // even nibbles (j=0,2,4,6)
        unsigned h = (w >> 4) & 0x0F0F0F0Fu;   // odd  nibbles (j=1,3,5,7)
        ulonglong2 pa = xp[2 * i];             // (x0,x1),(x2,x3)
        ulonglong2 pb = xp[2 * i + 1];         // (x4,x5),(x6,x7)
        qfma2<0x7440u>(acc0, e, h, pa.x);
        qfma2<0x7441u>(acc1, e, h, pa.y);
        qfma2<0x7442u>(acc2, e, h, pb.x);
        qfma2<0x7443u>(acc3, e, h, pb.y);
    }

    float2 a0 = ull_as_f2(acc0), a1 = ull_as_f2(acc1);
    float2 a2 = ull_as_f2(acc2), a3 = ull_as_f2(acc3);
    float tsum = ((a0.x + a0.y) + (a1.x + a1.y)) +
                 ((a2.x + a2.y) + (a3.x + a3.y));

    part[ksl][o_local] = tsum;
    __syncthreads();

    // ---- Epilogue: reduce warp slices, write deterministic partials ----
    if (tid < OUTS_PER_BLOCK) {
        float r = 0.0f;
        #pragma unroll
        for (int j = 0; j < KSLICES; j++) r += part[j][tid];
        g_part[blockIdx.y][blockIdx.x * OUTS_PER_BLOCK + tid] = r;
    }
    if (tid == BLOCK_THREADS - 1 && blockIdx.x == 0) {
        float xsp = 0.0f;
        #pragma unroll
        for (int j = 0; j < KSLICES; j++) xsp += wxsum[j];
        g_xsum[blockIdx.y] = xsp;
    }
}

__global__ __launch_bounds__(256)
void quant4linear_reduce(const float* __restrict__ scales,
                         const float* __restrict__ zeros,
                         const float* __restrict__ bias,
                         float*       __restrict__ out) {
    const int o = blockIdx.x * 256 + threadIdx.x;
    if (o >= OUT_FEATURES) return;

    float xst = (g_xsum[0] + g_xsum[1]) + (g_xsum[2] + g_xsum[3]);
    float r = (g_part[0][o] + g_part[1][o]) + (g_part[2][o] + g_part[3][o]);
    out[o] = r * scales[o] - xst * zeros[o] + bias[o];
}

extern "C" void kernel_launch(void* const* d_in, const int* in_sizes, int n_in,
                              void* d_out, int out_size) {
    const float* x       = (const float*)d_in[0];
    const int*   qweight = (const int*)d_in[1];
    const float* scales  = (const float*)d_in[2];
    const float* zeros   = (const float*)d_in[3];
    const float* bias    = (const float*)d_in[4];
    float* out = (float*)d_out;

    dim3 grid(OUT_FEATURES / OUTS_PER_BLOCK, KSPLIT);  // (344, 4) = 1376 blocks
    quant4linear_main<<<grid, BLOCK_THREADS>>>(x, qweight);

    quant4linear_reduce<<<(OUT_FEATURES + 255) / 256, 256>>>(scales, zeros,
                                                             bias, out);
}

// round 8
// speedup vs baseline: 1.1572x; 1.1572x over previous
#include <cuda_runtime.h>
#include <cstdint>

#define IN_FEATURES  4096
#define OUT_FEATURES 11008
#define WORDS        (IN_FEATURES / 8)        // 512 packed int32 rows
#define BLOCK_THREADS 256
#define OUTS_PER_BLOCK 64                     // 2 outputs per lane
#define GROUPS (OUT_FEATURES / OUTS_PER_BLOCK)  // 172
#define KSLICES 8                             // warps per block
#define KSPLIT  4                             // K-quarters across blockIdx.y
#define WORDS_PER_BLOCK (WORDS / KSPLIT)      // 128
#define WORDS_PER_WARP  (WORDS_PER_BLOCK / KSLICES)  // 16
#define XS_FLOATS (WORDS_PER_BLOCK * 8)       // 1024 floats staged per block

// Deterministic cross-block scratch (device globals are the allowed scratch).
__device__ float    g_part[KSPLIT][OUT_FEATURES];
__device__ float    g_xsumq[KSPLIT];
__device__ unsigned g_cnt[GROUPS];            // zero-init; self-resetting

// Packed constants: two fp32 lanes of -8388608.0f (0xCB000000)
#define NEG_MAGIC2 0xCB000000CB000000ull

// One packed pair of nibble-MACs:
//   lo = float(2^23 + nib_even) from byte SEL of e; hi likewise from h
//   f2 = (lo,hi) - (2^23,2^23)  exact (Sterbenz); acc2 += xpair * f2
template <unsigned SEL>
__device__ __forceinline__ void qfma2(unsigned long long& acc,
                                      unsigned e, unsigned h,
                                      unsigned long long xpair) {
    asm("{\n\t"
        ".reg .b32 lo, hi;\n\t"
        ".reg .b64 f2;\n\t"
        "prmt.b32 lo, %1, 0x4B000000, %3;\n\t"
        "prmt.b32 hi, %2, 0x4B000000, %3;\n\t"
        "mov.b64 f2, {lo, hi};\n\t"
        "add.rn.f32x2 f2, f2, %4;\n\t"
        "fma.rn.f32x2 %0, f2, %5, %0;\n\t"
        "}"
        : "+l"(acc)
        : "r"(e), "r"(h), "n"(SEL), "l"(NEG_MAGIC2), "l"(xpair));
}

__device__ __forceinline__ float2 ull_as_f2(unsigned long long a) {
    float2 r;
    r.x = __uint_as_float((unsigned)(a & 0xFFFFFFFFull));
    r.y = __uint_as_float((unsigned)(a >> 32));
    return r;
}

__global__ __launch_bounds__(BLOCK_THREADS, 4)
void quant4linear_fused(const float* __restrict__ x,
                        const int*   __restrict__ qweight,
                        const float* __restrict__ scales,
                        const float* __restrict__ zeros,
                        const float* __restrict__ bias,
                        float*       __restrict__ out) {
    __shared__ __align__(16) float xs[XS_FLOATS];
    __shared__ float wxsum[KSLICES];
    __shared__ float part[KSLICES][OUTS_PER_BLOCK];
    __shared__ unsigned s_ticket;

    const int tid   = threadIdx.x;
    const int lane  = tid & 31;
    const int ksl   = tid >> 5;
    const int bx    = blockIdx.x;                    // output group (172)
    const int by    = blockIdx.y;                    // K-quarter (4)
    const int kbase = by * WORDS_PER_BLOCK;
    const int obase = bx * OUTS_PER_BLOCK;

    // ---- Stage this block's x slice + partial x-sum ----
    float s = 0.0f;
    #pragma unroll
    for (int i = tid; i < XS_FLOATS; i += BLOCK_THREADS) {
        float v = x[kbase * 8 + i];
        xs[i] = v;
        s += v;
    }
    #pragma unroll
    for (int off = 16; off; off >>= 1)
        s += __shfl_down_sync(0xFFFFFFFFu, s, off);
    if (lane == 0) wxsum[ksl] = s;
    __syncthreads();

    if (tid == 0) {
        float xsp = 0.0f;
        #pragma unroll
        for (int j = 0; j < KSLICES; j++) xsp += wxsum[j];
        g_xsumq[by] = xsp;  // same value written by all blocks with this 'by'
    }

    // ---- Main loop: lane owns outputs obase+2*lane, obase+2*lane+1 ----
    const int2* wp = reinterpret_cast<const int2*>(
        qweight + (kbase + ksl * WORDS_PER_WARP) * OUT_FEATURES + obase) + lane;
    const ulonglong2* xp =
        reinterpret_cast<const ulonglong2*>(xs) + (ksl * WORDS_PER_WARP) * 2;

    unsigned long long a0 = 0, a1 = 0;  // output A: x-lanes (0,1)+(4,5) / (2,3)+(6,7)
    unsigned long long b0 = 0, b1 = 0;  // output B

    #pragma unroll 8
    for (int i = 0; i < WORDS_PER_WARP; i++) {
        int2 w2 = __ldg(wp);
        wp += OUT_FEATURES / 2;
        unsigned wa = (unsigned)w2.x, wb = (unsigned)w2.y;
        unsigned ea = wa & 0x0F0F0F0Fu, ha = (wa >> 4) & 0x0F0F0F0Fu;
        unsigned eb = wb & 0x0F0F0F0Fu, hb = (wb >> 4) & 0x0F0F0F0Fu;
        ulonglong2 pa = xp[2 * i];        // (x0,x1),(x2,x3)
        ulonglong2 pb = xp[2 * i + 1];    // (x4,x5),(x6,x7)
        qfma2<0x7440u>(a0, ea, ha, pa.x);
        qfma2<0x7441u>(a1, ea, ha, pa.y);
        qfma2<0x7442u>(a0, ea, ha, pb.x);
        qfma2<0x7443u>(a1, ea, ha, pb.y);
        qfma2<0x7440u>(b0, eb, hb, pa.x);
        qfma2<0x7441u>(b1, eb, hb, pa.y);
        qfma2<0x7442u>(b0, eb, hb, pb.x);
        qfma2<0x7443u>(b1, eb, hb, pb.y);
    }

    float2 fa0 = ull_as_f2(a0), fa1 = ull_as_f2(a1);
    float2 fb0 = ull_as_f2(b0), fb1 = ull_as_f2(b1);
    float2 tsum;
    tsum.x = (fa0.x + fa0.y) + (fa1.x + fa1.y);
    tsum.y = (fb0.x + fb0.y) + (fb1.x + fb1.y);
    *reinterpret_cast<float2*>(&part[ksl][2 * lane]) = tsum;
    __syncthreads();

    // ---- Block reduce over warps, publish K-quarter partial ----
    if (tid < OUTS_PER_BLOCK) {
        float r = 0.0f;
        #pragma unroll
        for (int j = 0; j < KSLICES; j++) r += part[j][tid];
        g_part[by][obase + tid] = r;
    }
    __syncthreads();

    // ---- Ticket: last K-quarter block of this group does the epilogue ----
    if (tid == 0) {
        unsigned t, one = 1u;
        asm volatile("atom.acq_rel.gpu.add.u32 %0, [%1], %2;"
                     : "=r"(t) : "l"(&g_cnt[bx]), "r"(one) : "memory");
        s_ticket = t;
    }
    __syncthreads();

    if (s_ticket == KSPLIT - 1) {
        if (tid < OUTS_PER_BLOCK) {
            int o = obase + tid;
            float r = (g_part[0][o] + g_part[1][o]) +
                      (g_part[2][o] + g_part[3][o]);
            float xst = (g_xsumq[0] + g_xsumq[1]) + (g_xsumq[2] + g_xsumq[3]);
            out[o] = r * scales[o] - xst * zeros[o] + bias[o];
        }
        if (tid == 0) g_cnt[bx] = 0;  // reset for next graph replay
    }
}

extern "C" void kernel_launch(void* const* d_in, const int* in_sizes, int n_in,
                              void* d_out, int out_size) {
    const float* x       = (const float*)d_in[0];
    const int*   qweight = (const int*)d_in[1];
    const float* scales  = (const float*)d_in[2];
    const float* zeros   = (const float*)d_in[3];
    const float* bias    = (const float*)d_in[4];
    float* out = (float*)d_out;

    dim3 grid(GROUPS, KSPLIT);  // (172, 4) = 688 blocks
    quant4linear_fused<<<grid, BLOCK_THREADS>>>(x, qweight, scales, zeros,
                                                bias, out);
}